// round 3
// baseline (speedup 1.0000x reference)
#include <cuda_runtime.h>
#include <math.h>

// GPT-2 small forward: B=2, T=1024, D=768, H=12, HD=64, L=12, V=50257
#define B_   2
#define T_   1024
#define D_   768
#define H_   12
#define HD_  64
#define L_   12
#define V_   50257
#define FF_  3072
#define BT_  (B_*T_)
#define EPS_ 1e-5f

// ---------------- scratch (no cudaMalloc allowed) ----------------
__device__ float g_x [BT_*D_];
__device__ float g_h [BT_*D_];
__device__ float g_q [BT_*D_];
__device__ float g_k [BT_*D_];
__device__ float g_v [BT_*D_];
__device__ float g_y [BT_*D_];
__device__ float g_ff[BT_*FF_];

// ---------------- embedding ----------------
__global__ void embed_kernel(const int* __restrict__ idx,
                             const float* __restrict__ tok,
                             const float* __restrict__ pos,
                             float* __restrict__ x) {
    int i = blockIdx.x * blockDim.x + threadIdx.x;
    if (i >= BT_*D_) return;
    int bt = i / D_, d = i - bt * D_;
    int t = bt % T_;
    x[i] = tok[(size_t)idx[bt]*D_ + d] + pos[(size_t)t*D_ + d];
}

// ---------------- layernorm (one block = one row, 256 thr, 3 elems/thr) ----------------
__global__ void ln_kernel(const float* __restrict__ x,
                          const float* __restrict__ g,
                          const float* __restrict__ b,
                          float* __restrict__ out) {
    __shared__ float red[256];
    int row = blockIdx.x;
    int tid = threadIdx.x;
    const float* xr = x + (size_t)row * D_;
    float v0 = xr[tid], v1 = xr[tid+256], v2 = xr[tid+512];
    red[tid] = v0 + v1 + v2;
    __syncthreads();
    #pragma unroll
    for (int s = 128; s > 0; s >>= 1) {
        if (tid < s) red[tid] += red[tid+s];
        __syncthreads();
    }
    float mean = red[0] * (1.0f / D_);
    __syncthreads();
    float d0 = v0-mean, d1 = v1-mean, d2 = v2-mean;
    red[tid] = d0*d0 + d1*d1 + d2*d2;
    __syncthreads();
    #pragma unroll
    for (int s = 128; s > 0; s >>= 1) {
        if (tid < s) red[tid] += red[tid+s];
        __syncthreads();
    }
    float rstd = rsqrtf(red[0] * (1.0f / D_) + EPS_);
    float* orow = out + (size_t)row * D_;
    orow[tid    ] = d0 * rstd * g[tid    ] + b[tid    ];
    orow[tid+256] = d1 * rstd * g[tid+256] + b[tid+256];
    orow[tid+512] = d2 * rstd * g[tid+512] + b[tid+512];
}

// ---------------- SGEMM: C[M,N] = A[M,K] @ W[K,N] (+bias)(+gelu)(+residual) ----------------
// 128x128 block tile, BK=8, 256 threads, 8x8 microtile per thread.
// blockIdx.x = row-block (fast dim -> col strips of W reused in L2 across row blocks)
// M must be a multiple of 128 (always 2048 here); N may be ragged (V=50257); K % 8 == 0.
template<int BIAS, int RES, int GELU>
__global__ __launch_bounds__(256, 2)
void gemm_kernel(const float* __restrict__ A, const float* __restrict__ W,
                 const float* __restrict__ bias, const float* __restrict__ res,
                 float* __restrict__ C, int M, int N, int K) {
    __shared__ float As[8][128];
    __shared__ float Bs[8][128];

    int tid = threadIdx.x;
    int bm = blockIdx.x * 128;
    int bn = blockIdx.y * 128;
    int tx = tid & 15;          // 0..15 -> col microtile
    int ty = tid >> 4;          // 0..15 -> row microtile

    int ar = tid >> 1;          // 0..127  A row within tile
    int ak = (tid & 1) * 4;     // 0 or 4  A k offset
    int bk = tid >> 5;          // 0..7    W k row within tile
    int bc = (tid & 31) * 4;    // 0..124  W col offset

    float acc[8][8];
    #pragma unroll
    for (int i = 0; i < 8; i++)
        #pragma unroll
        for (int j = 0; j < 8; j++) acc[i][j] = 0.0f;

    const float* Arow = A + (size_t)(bm + ar) * K + ak;

    for (int k0 = 0; k0 < K; k0 += 8) {
        // A tile (vectorized, always in-bounds)
        float4 av = *(const float4*)(Arow + k0);
        As[ak+0][ar] = av.x; As[ak+1][ar] = av.y;
        As[ak+2][ar] = av.z; As[ak+3][ar] = av.w;
        // W tile (scalar, N may be ragged)
        {
            const float* Wr = W + (size_t)(k0 + bk) * N;
            #pragma unroll
            for (int c = 0; c < 4; c++) {
                int col = bn + bc + c;
                Bs[bk][bc + c] = (col < N) ? Wr[col] : 0.0f;
            }
        }
        __syncthreads();
        #pragma unroll
        for (int k = 0; k < 8; k++) {
            float a[8], bb[8];
            #pragma unroll
            for (int i = 0; i < 8; i++) a[i]  = As[k][ty*8 + i];
            #pragma unroll
            for (int j = 0; j < 8; j++) bb[j] = Bs[k][tx*8 + j];
            #pragma unroll
            for (int i = 0; i < 8; i++)
                #pragma unroll
                for (int j = 0; j < 8; j++)
                    acc[i][j] += a[i] * bb[j];
        }
        __syncthreads();
    }

    #pragma unroll
    for (int i = 0; i < 8; i++) {
        int row = bm + ty*8 + i;
        #pragma unroll
        for (int j = 0; j < 8; j++) {
            int col = bn + tx*8 + j;
            if (col < N) {
                float v = acc[i][j];
                if (BIAS) v += bias[col];
                if (GELU) v = 0.5f * v * (1.0f + erff(v * 0.70710678118654752f));
                if (RES)  v += res[(size_t)row * N + col];
                C[(size_t)row * N + col] = v;
            }
        }
    }
}

// ---------------- causal attention: one block per (query t, head h, batch b) ----------------
// q,k,v,y layout: [B*T, D] with head h at column offset h*HD (no transposes needed).
__global__ void attn_kernel(const float* __restrict__ q, const float* __restrict__ k,
                            const float* __restrict__ v, float* __restrict__ y) {
    __shared__ float sQ[HD_];
    __shared__ float sS[T_];
    __shared__ float red[128];

    int t = blockIdx.x, h = blockIdx.y, b = blockIdx.z;
    int tid = threadIdx.x;
    const size_t qoff = (size_t)(b*T_ + t) * D_ + h*HD_;

    if (tid < HD_) sQ[tid] = q[qoff + tid];
    __syncthreads();

    // scores for j <= t, track local max
    float lmax = -INFINITY;
    for (int j = tid; j <= t; j += 128) {
        const float* kr = k + (size_t)(b*T_ + j) * D_ + h*HD_;
        float acc = 0.0f;
        #pragma unroll
        for (int d = 0; d < HD_; d += 4) {
            float4 kv = *(const float4*)(kr + d);
            acc += sQ[d]*kv.x + sQ[d+1]*kv.y + sQ[d+2]*kv.z + sQ[d+3]*kv.w;
        }
        acc *= 0.125f;              // 1/sqrt(64)
        sS[j] = acc;
        lmax = fmaxf(lmax, acc);
    }
    red[tid] = lmax;
    __syncthreads();
    #pragma unroll
    for (int s = 64; s > 0; s >>= 1) {
        if (tid < s) red[tid] = fmaxf(red[tid], red[tid+s]);
        __syncthreads();
    }
    float mx = red[0];
    __syncthreads();

    float lsum = 0.0f;
    for (int j = tid; j <= t; j += 128) {
        float e = __expf(sS[j] - mx);
        sS[j] = e;
        lsum += e;
    }
    red[tid] = lsum;
    __syncthreads();
    #pragma unroll
    for (int s = 64; s > 0; s >>= 1) {
        if (tid < s) red[tid] += red[tid+s];
        __syncthreads();
    }
    float inv = 1.0f / red[0];
    __syncthreads();

    // y[d] = sum_j p[j] * v[j][d]; 128 threads = 2 j-strides x 64 dims
    int d = tid & 63;
    int half = tid >> 6;
    float acc = 0.0f;
    for (int j = half; j <= t; j += 2)
        acc += sS[j] * v[(size_t)(b*T_ + j) * D_ + h*HD_ + d];
    red[tid] = acc;
    __syncthreads();
    if (tid < 64)
        y[qoff + tid] = (red[tid] + red[tid + 64]) * inv;
}

// ---------------- host orchestration ----------------
static inline dim3 gemm_grid(int M, int N) {
    return dim3(M / 128, (N + 127) / 128);
}

extern "C" void kernel_launch(void* const* d_in, const int* in_sizes, int n_in,
                              void* d_out, int out_size) {
    const int*   idx  = (const int*)  d_in[0];
    const float* tok  = (const float*)d_in[1];
    const float* pos  = (const float*)d_in[2];
    const float* Wq   = (const float*)d_in[3];
    const float* Wk   = (const float*)d_in[4];
    const float* Wv   = (const float*)d_in[5];
    const float* Wo   = (const float*)d_in[6];
    const float* bo   = (const float*)d_in[7];
    const float* ln1g = (const float*)d_in[8];
    const float* ln1b = (const float*)d_in[9];
    const float* Wf1  = (const float*)d_in[10];
    const float* bf1  = (const float*)d_in[11];
    const float* Wf2  = (const float*)d_in[12];
    const float* bf2  = (const float*)d_in[13];
    const float* ln2g = (const float*)d_in[14];
    const float* ln2b = (const float*)d_in[15];
    const float* lnfg = (const float*)d_in[16];
    const float* lnfb = (const float*)d_in[17];
    const float* Wlm  = (const float*)d_in[18];
    float* out = (float*)d_out;

    float *x, *h, *qb, *kb, *vb, *yb, *ffb;
    cudaGetSymbolAddress((void**)&x,   g_x);
    cudaGetSymbolAddress((void**)&h,   g_h);
    cudaGetSymbolAddress((void**)&qb,  g_q);
    cudaGetSymbolAddress((void**)&kb,  g_k);
    cudaGetSymbolAddress((void**)&vb,  g_v);
    cudaGetSymbolAddress((void**)&yb,  g_y);
    cudaGetSymbolAddress((void**)&ffb, g_ff);

    // x = tok_emb[idx] + pos_emb
    embed_kernel<<<(BT_*D_ + 255)/256, 256>>>(idx, tok, pos, x);

    for (int l = 0; l < L_; l++) {
        const float* wq = Wq + (size_t)l*D_*D_;
        const float* wk = Wk + (size_t)l*D_*D_;
        const float* wv = Wv + (size_t)l*D_*D_;
        const float* wo = Wo + (size_t)l*D_*D_;
        const float* wf1 = Wf1 + (size_t)l*D_*FF_;
        const float* wf2 = Wf2 + (size_t)l*FF_*D_;

        // h = LN1(x)
        ln_kernel<<<BT_, 256>>>(x, ln1g + l*D_, ln1b + l*D_, h);
        // q,k,v = h @ W{q,k,v}
        gemm_kernel<0,0,0><<<gemm_grid(BT_, D_), 256>>>(h, wq, nullptr, nullptr, qb, BT_, D_, D_);
        gemm_kernel<0,0,0><<<gemm_grid(BT_, D_), 256>>>(h, wk, nullptr, nullptr, kb, BT_, D_, D_);
        gemm_kernel<0,0,0><<<gemm_grid(BT_, D_), 256>>>(h, wv, nullptr, nullptr, vb, BT_, D_, D_);
        // y = causal attention(q,k,v)
        attn_kernel<<<dim3(T_, H_, B_), 128>>>(qb, kb, vb, yb);
        // x = x + y @ Wo + bo   (in-place residual)
        gemm_kernel<1,1,0><<<gemm_grid(BT_, D_), 256>>>(yb, wo, bo + l*D_, x, x, BT_, D_, D_);
        // h = LN2(x)
        ln_kernel<<<BT_, 256>>>(x, ln2g + l*D_, ln2b + l*D_, h);
        // ff = gelu(h @ Wf1 + bf1)
        gemm_kernel<1,0,1><<<gemm_grid(BT_, FF_), 256>>>(h, wf1, bf1 + l*FF_, nullptr, ffb, BT_, FF_, D_);
        // x = x + ff @ Wf2 + bf2
        gemm_kernel<1,1,0><<<gemm_grid(BT_, D_), 256>>>(ffb, wf2, bf2 + l*D_, x, x, BT_, D_, FF_);
    }

    // h = LN_f(x); logits = h @ W_lm -> d_out
    ln_kernel<<<BT_, 256>>>(x, lnfg, lnfb, h);
    gemm_kernel<0,0,0><<<gemm_grid(BT_, V_), 256>>>(h, Wlm, nullptr, nullptr, out, BT_, V_, D_);
}

// round 4
// speedup vs baseline: 1.3029x; 1.3029x over previous
#include <cuda_runtime.h>
#include <math.h>

// GPT-2 small forward: B=2, T=1024, D=768, H=12, HD=64, L=12, V=50257
#define B_   2
#define T_   1024
#define D_   768
#define H_   12
#define HD_  64
#define L_   12
#define V_   50257
#define FF_  3072
#define BT_  (B_*T_)
#define EPS_ 1e-5f

typedef unsigned long long ull;

// ---------------- packed f32x2 helpers (Blackwell FFMA2 path) ----------------
__device__ __forceinline__ ull pack2(float x, float y) {
    ull r;
    asm("mov.b64 %0, {%1, %2};" : "=l"(r)
        : "r"(__float_as_uint(x)), "r"(__float_as_uint(y)));
    return r;
}
__device__ __forceinline__ ull splat2(float x) {
    ull r;
    asm("mov.b64 %0, {%1, %1};" : "=l"(r) : "r"(__float_as_uint(x)));
    return r;
}
__device__ __forceinline__ void fma2(ull& d, ull a, ull b) {
    asm("fma.rn.f32x2 %0, %1, %2, %0;" : "+l"(d) : "l"(a), "l"(b));
}
__device__ __forceinline__ void unpack2(ull v, float& lo, float& hi) {
    unsigned a, b;
    asm("mov.b64 {%0, %1}, %2;" : "=r"(a), "=r"(b) : "l"(v));
    lo = __uint_as_float(a); hi = __uint_as_float(b);
}

// ---------------- scratch (no cudaMalloc allowed) ----------------
__device__ float g_x [BT_*D_];
__device__ float g_h [BT_*D_];
__device__ float g_q [BT_*D_];
__device__ float g_k [BT_*D_];
__device__ float g_v [BT_*D_];
__device__ float g_y [BT_*D_];
__device__ float g_ff[BT_*FF_];

// ---------------- embedding ----------------
__global__ void embed_kernel(const int* __restrict__ idx,
                             const float* __restrict__ tok,
                             const float* __restrict__ pos,
                             float* __restrict__ x) {
    int i = blockIdx.x * blockDim.x + threadIdx.x;
    if (i >= BT_*D_) return;
    int bt = i / D_, d = i - bt * D_;
    int t = bt % T_;
    x[i] = tok[(size_t)idx[bt]*D_ + d] + pos[(size_t)t*D_ + d];
}

// ---------------- layernorm (one block = one row, 256 thr, 3 elems/thr) ----------------
__global__ void ln_kernel(const float* __restrict__ x,
                          const float* __restrict__ g,
                          const float* __restrict__ b,
                          float* __restrict__ out) {
    __shared__ float red[256];
    int row = blockIdx.x;
    int tid = threadIdx.x;
    const float* xr = x + (size_t)row * D_;
    float v0 = xr[tid], v1 = xr[tid+256], v2 = xr[tid+512];
    red[tid] = v0 + v1 + v2;
    __syncthreads();
    #pragma unroll
    for (int s = 128; s > 0; s >>= 1) {
        if (tid < s) red[tid] += red[tid+s];
        __syncthreads();
    }
    float mean = red[0] * (1.0f / D_);
    __syncthreads();
    float d0 = v0-mean, d1 = v1-mean, d2 = v2-mean;
    red[tid] = d0*d0 + d1*d1 + d2*d2;
    __syncthreads();
    #pragma unroll
    for (int s = 128; s > 0; s >>= 1) {
        if (tid < s) red[tid] += red[tid+s];
        __syncthreads();
    }
    float rstd = rsqrtf(red[0] * (1.0f / D_) + EPS_);
    float* orow = out + (size_t)row * D_;
    orow[tid    ] = d0 * rstd * g[tid    ] + b[tid    ];
    orow[tid+256] = d1 * rstd * g[tid+256] + b[tid+256];
    orow[tid+512] = d2 * rstd * g[tid+512] + b[tid+512];
}

// ---------------- f32x2 SGEMM: C[M,N] = A[M,K] @ W[K,N] (+bias)(+gelu)(+residual) ----------------
// BMxBN block tile, BK=8, double-buffered SMEM, packed fma.rn.f32x2 inner product.
// Thread microtile: 8 rows (as 4 row-pairs) x NQ*4 cols. Threads = 2*BM.
// M % BM == 0, K % 8 == 0; N may be ragged (vector B path auto-disabled).
template<int BM, int BN, int NQ, int BIAS, int RES, int GELU>
__global__ __launch_bounds__(2*BM, (BM==128) ? 2 : 4)
void gemm_kernel(const float* __restrict__ A, const float* __restrict__ W,
                 const float* __restrict__ bias, const float* __restrict__ res,
                 float* __restrict__ C, int M, int N, int K) {
    __shared__ float As[2][8][BM];
    __shared__ float Bs[2][8][BN];

    int tid = threadIdx.x;
    int bm = blockIdx.x * BM;
    int bn = blockIdx.y * BN;
    int tx = tid & 15;              // col quad within 64-col group
    int ty = tid >> 4;              // row octet: rows ty*8 .. ty*8+7

    int ar = tid >> 1;              // A row within tile
    int ak = (tid & 1) * 4;         // A k offset (0 or 4)
    int bk = tid / (BN/4);          // W k row within tile (0..7)
    int bc = (tid % (BN/4)) * 4;    // W col offset

    ull acc[4][NQ*4];
    #pragma unroll
    for (int p = 0; p < 4; p++)
        #pragma unroll
        for (int q = 0; q < NQ*4; q++) acc[p][q] = 0ull;  // two packed +0.0f

    const float* Arow = A + (size_t)(bm + ar) * K + ak;
    bool vecB = ((N & 3) == 0) && (bn + BN <= N);

    // ---- preload first k-tile into buffer 0 ----
    {
        float4 av = *(const float4*)(Arow);
        As[0][ak+0][ar] = av.x; As[0][ak+1][ar] = av.y;
        As[0][ak+2][ar] = av.z; As[0][ak+3][ar] = av.w;
        const float* Wr = W + (size_t)bk * N;
        if (vecB) {
            *(float4*)&Bs[0][bk][bc] = *(const float4*)(Wr + bn + bc);
        } else {
            #pragma unroll
            for (int c = 0; c < 4; c++) {
                int col = bn + bc + c;
                Bs[0][bk][bc+c] = (col < N) ? Wr[col] : 0.0f;
            }
        }
    }
    __syncthreads();

    int buf = 0;
    for (int k0 = 0; k0 < K; k0 += 8) {
        float4 avn; float4 bvn; float bsc[4];
        bool nxt = (k0 + 8 < K);
        if (nxt) {
            avn = *(const float4*)(Arow + k0 + 8);
            const float* Wr = W + (size_t)(k0 + 8 + bk) * N;
            if (vecB) {
                bvn = *(const float4*)(Wr + bn + bc);
            } else {
                #pragma unroll
                for (int c = 0; c < 4; c++) {
                    int col = bn + bc + c;
                    bsc[c] = (col < N) ? Wr[col] : 0.0f;
                }
            }
        }
        // ---- compute on current buffer ----
        #pragma unroll
        for (int k = 0; k < 8; k++) {
            float4 A0 = *(const float4*)&As[buf][k][ty*8];
            float4 A1 = *(const float4*)&As[buf][k][ty*8 + 4];
            ull a[4];
            a[0] = pack2(A0.x, A0.y); a[1] = pack2(A0.z, A0.w);
            a[2] = pack2(A1.x, A1.y); a[3] = pack2(A1.z, A1.w);
            ull bsp[NQ*4];
            #pragma unroll
            for (int q = 0; q < NQ; q++) {
                float4 bq = *(const float4*)&Bs[buf][k][q*64 + tx*4];
                bsp[q*4+0] = splat2(bq.x); bsp[q*4+1] = splat2(bq.y);
                bsp[q*4+2] = splat2(bq.z); bsp[q*4+3] = splat2(bq.w);
            }
            #pragma unroll
            for (int p = 0; p < 4; p++)
                #pragma unroll
                for (int q = 0; q < NQ*4; q++)
                    fma2(acc[p][q], a[p], bsp[q]);
        }
        // ---- stage next tile ----
        if (nxt) {
            int nb = buf ^ 1;
            As[nb][ak+0][ar] = avn.x; As[nb][ak+1][ar] = avn.y;
            As[nb][ak+2][ar] = avn.z; As[nb][ak+3][ar] = avn.w;
            if (vecB) {
                *(float4*)&Bs[nb][bk][bc] = bvn;
            } else {
                #pragma unroll
                for (int c = 0; c < 4; c++) Bs[nb][bk][bc+c] = bsc[c];
            }
            __syncthreads();
            buf = nb;
        }
    }

    // ---- epilogue ----
    #pragma unroll
    for (int p = 0; p < 4; p++) {
        int r0 = bm + ty*8 + 2*p;           // row pair (r0, r0+1)
        #pragma unroll
        for (int q = 0; q < NQ; q++)
            #pragma unroll
            for (int j = 0; j < 4; j++) {
                int col = bn + q*64 + tx*4 + j;
                if (col < N) {
                    float v0, v1;
                    unpack2(acc[p][q*4+j], v0, v1);
                    if (BIAS) { float bb = bias[col]; v0 += bb; v1 += bb; }
                    if (GELU) {
                        v0 = 0.5f * v0 * (1.0f + erff(v0 * 0.70710678118654752f));
                        v1 = 0.5f * v1 * (1.0f + erff(v1 * 0.70710678118654752f));
                    }
                    if (RES) {
                        v0 += res[(size_t)r0 * N + col];
                        v1 += res[(size_t)(r0+1) * N + col];
                    }
                    C[(size_t)r0 * N + col]     = v0;
                    C[(size_t)(r0+1) * N + col] = v1;
                }
            }
    }
}

// ---------------- causal attention: one block per (query t, head h, batch b) ----------------
__global__ void attn_kernel(const float* __restrict__ q, const float* __restrict__ k,
                            const float* __restrict__ v, float* __restrict__ y) {
    __shared__ float sQ[HD_];
    __shared__ float sS[T_];
    __shared__ float red[128];

    int t = blockIdx.x, h = blockIdx.y, b = blockIdx.z;
    int tid = threadIdx.x;
    const size_t qoff = (size_t)(b*T_ + t) * D_ + h*HD_;

    if (tid < HD_) sQ[tid] = q[qoff + tid];
    __syncthreads();

    float lmax = -INFINITY;
    for (int j = tid; j <= t; j += 128) {
        const float* kr = k + (size_t)(b*T_ + j) * D_ + h*HD_;
        float acc = 0.0f;
        #pragma unroll
        for (int d = 0; d < HD_; d += 4) {
            float4 kv = *(const float4*)(kr + d);
            acc += sQ[d]*kv.x + sQ[d+1]*kv.y + sQ[d+2]*kv.z + sQ[d+3]*kv.w;
        }
        acc *= 0.125f;
        sS[j] = acc;
        lmax = fmaxf(lmax, acc);
    }
    red[tid] = lmax;
    __syncthreads();
    #pragma unroll
    for (int s = 64; s > 0; s >>= 1) {
        if (tid < s) red[tid] = fmaxf(red[tid], red[tid+s]);
        __syncthreads();
    }
    float mx = red[0];
    __syncthreads();

    float lsum = 0.0f;
    for (int j = tid; j <= t; j += 128) {
        float e = __expf(sS[j] - mx);
        sS[j] = e;
        lsum += e;
    }
    red[tid] = lsum;
    __syncthreads();
    #pragma unroll
    for (int s = 64; s > 0; s >>= 1) {
        if (tid < s) red[tid] += red[tid+s];
        __syncthreads();
    }
    float inv = 1.0f / red[0];
    __syncthreads();

    int d = tid & 63;
    int half = tid >> 6;
    float acc = 0.0f;
    for (int j = half; j <= t; j += 2)
        acc += sS[j] * v[(size_t)(b*T_ + j) * D_ + h*HD_ + d];
    red[tid] = acc;
    __syncthreads();
    if (tid < 64)
        y[qoff + tid] = (red[tid] + red[tid + 64]) * inv;
}

// ---------------- host orchestration ----------------
extern "C" void kernel_launch(void* const* d_in, const int* in_sizes, int n_in,
                              void* d_out, int out_size) {
    const int*   idx  = (const int*)  d_in[0];
    const float* tok  = (const float*)d_in[1];
    const float* pos  = (const float*)d_in[2];
    const float* Wq   = (const float*)d_in[3];
    const float* Wk   = (const float*)d_in[4];
    const float* Wv   = (const float*)d_in[5];
    const float* Wo   = (const float*)d_in[6];
    const float* bo   = (const float*)d_in[7];
    const float* ln1g = (const float*)d_in[8];
    const float* ln1b = (const float*)d_in[9];
    const float* Wf1  = (const float*)d_in[10];
    const float* bf1  = (const float*)d_in[11];
    const float* Wf2  = (const float*)d_in[12];
    const float* bf2  = (const float*)d_in[13];
    const float* ln2g = (const float*)d_in[14];
    const float* ln2b = (const float*)d_in[15];
    const float* lnfg = (const float*)d_in[16];
    const float* lnfb = (const float*)d_in[17];
    const float* Wlm  = (const float*)d_in[18];
    float* out = (float*)d_out;

    float *x, *h, *qb, *kb, *vb, *yb, *ffb;
    cudaGetSymbolAddress((void**)&x,   g_x);
    cudaGetSymbolAddress((void**)&h,   g_h);
    cudaGetSymbolAddress((void**)&qb,  g_q);
    cudaGetSymbolAddress((void**)&kb,  g_k);
    cudaGetSymbolAddress((void**)&vb,  g_v);
    cudaGetSymbolAddress((void**)&yb,  g_y);
    cudaGetSymbolAddress((void**)&ffb, g_ff);

    const dim3 gS(BT_/64, D_/64);       // 32 x 12 = 384 blocks (N=768 gemms)
    const dim3 gF1(BT_/128, FF_/128);   // 16 x 24 = 384 blocks
    const dim3 gLM(BT_/128, (V_+127)/128); // 16 x 393

    embed_kernel<<<(BT_*D_ + 255)/256, 256>>>(idx, tok, pos, x);

    for (int l = 0; l < L_; l++) {
        const float* wq  = Wq  + (size_t)l*D_*D_;
        const float* wk  = Wk  + (size_t)l*D_*D_;
        const float* wv  = Wv  + (size_t)l*D_*D_;
        const float* wo  = Wo  + (size_t)l*D_*D_;
        const float* wf1 = Wf1 + (size_t)l*D_*FF_;
        const float* wf2 = Wf2 + (size_t)l*FF_*D_;

        ln_kernel<<<BT_, 256>>>(x, ln1g + l*D_, ln1b + l*D_, h);
        gemm_kernel<64,64,1,0,0,0><<<gS, 128>>>(h, wq, nullptr, nullptr, qb, BT_, D_, D_);
        gemm_kernel<64,64,1,0,0,0><<<gS, 128>>>(h, wk, nullptr, nullptr, kb, BT_, D_, D_);
        gemm_kernel<64,64,1,0,0,0><<<gS, 128>>>(h, wv, nullptr, nullptr, vb, BT_, D_, D_);
        attn_kernel<<<dim3(T_, H_, B_), 128>>>(qb, kb, vb, yb);
        gemm_kernel<64,64,1,1,1,0><<<gS, 128>>>(yb, wo, bo + l*D_, x, x, BT_, D_, D_);
        ln_kernel<<<BT_, 256>>>(x, ln2g + l*D_, ln2b + l*D_, h);
        gemm_kernel<128,128,2,1,0,1><<<gF1, 256>>>(h, wf1, bf1 + l*FF_, nullptr, ffb, BT_, FF_, D_);
        gemm_kernel<64,64,1,1,1,0><<<gS, 128>>>(ffb, wf2, bf2 + l*D_, x, x, BT_, D_, FF_);
    }

    ln_kernel<<<BT_, 256>>>(x, lnfg, lnfb, h);
    gemm_kernel<128,128,2,0,0,0><<<gLM, 256>>>(h, Wlm, nullptr, nullptr, out, BT_, V_, D_);
}

// round 8
// speedup vs baseline: 1.6376x; 1.2569x over previous
#include <cuda_runtime.h>
#include <math.h>

// GPT-2 small forward: B=2, T=1024, D=768, H=12, HD=64, L=12, V=50257
#define B_   2
#define T_   1024
#define D_   768
#define H_   12
#define HD_  64
#define L_   12
#define V_   50257
#define FF_  3072
#define BT_  (B_*T_)
#define EPS_ 1e-5f

// ---------------- scratch (no cudaMalloc allowed) ----------------
__device__ float g_x [BT_*D_];
__device__ float g_h [BT_*D_];
__device__ float g_q [BT_*D_];
__device__ float g_k [BT_*D_];
__device__ float g_v [BT_*D_];
__device__ float g_y [BT_*D_];
__device__ float g_ff[BT_*FF_];

// ---------------- tf32 helpers ----------------
__device__ __forceinline__ unsigned f2tf32(float f) {
    unsigned u;
    asm("cvt.rna.tf32.f32 %0, %1;" : "=r"(u) : "f"(f));
    return u;
}
__device__ __forceinline__ void mma_tf32(float* c, const unsigned* a, const unsigned* b) {
    asm volatile(
        "mma.sync.aligned.m16n8k8.row.col.f32.tf32.tf32.f32 "
        "{%0,%1,%2,%3}, {%4,%5,%6,%7}, {%8,%9}, {%0,%1,%2,%3};"
        : "+f"(c[0]), "+f"(c[1]), "+f"(c[2]), "+f"(c[3])
        : "r"(a[0]), "r"(a[1]), "r"(a[2]), "r"(a[3]), "r"(b[0]), "r"(b[1]));
}

// ---------------- embedding ----------------
__global__ void embed_kernel(const int* __restrict__ idx,
                             const float* __restrict__ tok,
                             const float* __restrict__ pos,
                             float* __restrict__ x) {
    int i = blockIdx.x * blockDim.x + threadIdx.x;
    if (i >= BT_*D_) return;
    int bt = i / D_, d = i - bt * D_;
    int t = bt % T_;
    x[i] = tok[(size_t)idx[bt]*D_ + d] + pos[(size_t)t*D_ + d];
}

// ---------------- layernorm ----------------
__global__ void ln_kernel(const float* __restrict__ x,
                          const float* __restrict__ g,
                          const float* __restrict__ b,
                          float* __restrict__ out) {
    __shared__ float red[256];
    int row = blockIdx.x;
    int tid = threadIdx.x;
    const float* xr = x + (size_t)row * D_;
    float v0 = xr[tid], v1 = xr[tid+256], v2 = xr[tid+512];
    red[tid] = v0 + v1 + v2;
    __syncthreads();
    #pragma unroll
    for (int s = 128; s > 0; s >>= 1) {
        if (tid < s) red[tid] += red[tid+s];
        __syncthreads();
    }
    float mean = red[0] * (1.0f / D_);
    __syncthreads();
    float d0 = v0-mean, d1 = v1-mean, d2 = v2-mean;
    red[tid] = d0*d0 + d1*d1 + d2*d2;
    __syncthreads();
    #pragma unroll
    for (int s = 128; s > 0; s >>= 1) {
        if (tid < s) red[tid] += red[tid+s];
        __syncthreads();
    }
    float rstd = rsqrtf(red[0] * (1.0f / D_) + EPS_);
    float* orow = out + (size_t)row * D_;
    orow[tid    ] = d0 * rstd * g[tid    ] + b[tid    ];
    orow[tid+256] = d1 * rstd * g[tid+256] + b[tid+256];
    orow[tid+512] = d2 * rstd * g[tid+512] + b[tid+512];
}

// ---------------- tf32 tensor-core GEMM ----------------
// C[M,N] = A[M,K] @ W[K,N] (+bias)(+gelu)(+residual)
// Block tile BMxBN, k-tile BK, warp tile WMxWN, m16n8k8 tf32 mma, fp32 accum.
// A staged [BM][BK+1] (tf32 bits); W staged transposed [BN][BK+1].
// M % BM == 0, K % BK == 0; N may be ragged / unaligned (scalar B path).
template<int BM, int BN, int BK, int WM, int WN, int BIAS, int RES, int GELU>
__global__ __launch_bounds__(32*(BM/WM)*(BN/WN))
void mma_gemm(const float* __restrict__ A, const float* __restrict__ W,
              const float* __restrict__ bias, const float* __restrict__ res,
              float* __restrict__ C, int M, int N, int K) {
    constexpr int NWM = BM / WM;
    constexpr int NWN = BN / WN;
    constexpr int NT  = 32 * NWM * NWN;
    constexpr int MT  = WM / 16;          // m16 tiles per warp
    constexpr int NTn = WN / 8;           // n8 tiles per warp
    constexpr int KK  = BK / 8;           // k8 steps per k-tile
    constexpr int BK1 = BK + 1;           // pad against bank conflicts
    constexpr int QA  = BM * BK / 4 / NT; // float4 loads per thread (A)
    constexpr int QB  = BK * BN / 4 / NT; // float4-equivalent loads per thread (B)

    __shared__ unsigned As[2][BM * BK1];
    __shared__ unsigned Bs[2][BN * BK1];

    const int tid = threadIdx.x;
    const int wid = tid >> 5;
    const int lane = tid & 31;
    const int g   = lane >> 2;            // group id (0..7)
    const int tig = lane & 3;             // thread in group (0..3)
    const int warp_m = wid % NWM;
    const int warp_n = wid / NWM;
    const int bm = blockIdx.x * BM;
    const int bn = blockIdx.y * BN;
    // float4 B loads only when every address is 16B-aligned and in-bounds:
    // requires N % 4 == 0 (row stride alignment) and a full tile.
    const bool vecB = ((N & 3) == 0) && (bn + BN <= N);

    float acc[MT][NTn][4];
    #pragma unroll
    for (int i = 0; i < MT; i++)
        #pragma unroll
        for (int j = 0; j < NTn; j++)
            #pragma unroll
            for (int c = 0; c < 4; c++) acc[i][j][c] = 0.0f;

    // ---- prologue: stage k-tile 0 into buffer 0 ----
    #pragma unroll
    for (int i = 0; i < QA; i++) {
        int idx = tid + i * NT;
        int r  = idx / (BK/4);
        int kq = (idx % (BK/4)) * 4;
        float4 v = *(const float4*)(A + (size_t)(bm + r) * K + kq);
        unsigned* p = &As[0][r * BK1 + kq];
        p[0] = f2tf32(v.x); p[1] = f2tf32(v.y); p[2] = f2tf32(v.z); p[3] = f2tf32(v.w);
    }
    #pragma unroll
    for (int i = 0; i < QB; i++) {
        int idx = tid + i * NT;
        int k  = idx / (BN/4);
        int nq = (idx % (BN/4)) * 4;
        const float* Wr = W + (size_t)k * N;
        float v[4];
        if (vecB) {
            float4 t = *(const float4*)(Wr + bn + nq);
            v[0] = t.x; v[1] = t.y; v[2] = t.z; v[3] = t.w;
        } else {
            #pragma unroll
            for (int c = 0; c < 4; c++) {
                int col = bn + nq + c;
                v[c] = (col < N) ? Wr[col] : 0.0f;
            }
        }
        #pragma unroll
        for (int c = 0; c < 4; c++) Bs[0][(nq + c) * BK1 + k] = f2tf32(v[c]);
    }
    __syncthreads();

    int buf = 0;
    for (int k0 = 0; k0 < K; k0 += BK) {
        const bool nxt = (k0 + BK < K);
        float4 pa[QA]; float pb[QB][4];
        if (nxt) {
            #pragma unroll
            for (int i = 0; i < QA; i++) {
                int idx = tid + i * NT;
                int r  = idx / (BK/4);
                int kq = (idx % (BK/4)) * 4;
                pa[i] = *(const float4*)(A + (size_t)(bm + r) * K + k0 + BK + kq);
            }
            #pragma unroll
            for (int i = 0; i < QB; i++) {
                int idx = tid + i * NT;
                int k  = idx / (BN/4);
                int nq = (idx % (BN/4)) * 4;
                const float* Wr = W + (size_t)(k0 + BK + k) * N;
                if (vecB) {
                    float4 t = *(const float4*)(Wr + bn + nq);
                    pb[i][0] = t.x; pb[i][1] = t.y; pb[i][2] = t.z; pb[i][3] = t.w;
                } else {
                    #pragma unroll
                    for (int c = 0; c < 4; c++) {
                        int col = bn + nq + c;
                        pb[i][c] = (col < N) ? Wr[col] : 0.0f;
                    }
                }
            }
        }
        // ---- compute on current buffer ----
        #pragma unroll
        for (int kk = 0; kk < KK; kk++) {
            unsigned afr[MT][4];
            #pragma unroll
            for (int mt = 0; mt < MT; mt++) {
                int rm = warp_m * WM + mt * 16;
                const unsigned* base = &As[buf][0];
                afr[mt][0] = base[(rm + g    ) * BK1 + kk*8 + tig    ];
                afr[mt][1] = base[(rm + g + 8) * BK1 + kk*8 + tig    ];
                afr[mt][2] = base[(rm + g    ) * BK1 + kk*8 + tig + 4];
                afr[mt][3] = base[(rm + g + 8) * BK1 + kk*8 + tig + 4];
            }
            unsigned bfr[NTn][2];
            #pragma unroll
            for (int nt = 0; nt < NTn; nt++) {
                int cn = warp_n * WN + nt * 8;
                const unsigned* base = &Bs[buf][0];
                bfr[nt][0] = base[(cn + g) * BK1 + kk*8 + tig    ];
                bfr[nt][1] = base[(cn + g) * BK1 + kk*8 + tig + 4];
            }
            #pragma unroll
            for (int mt = 0; mt < MT; mt++)
                #pragma unroll
                for (int nt = 0; nt < NTn; nt++)
                    mma_tf32(acc[mt][nt], afr[mt], bfr[nt]);
        }
        // ---- store prefetched tile to the other buffer ----
        if (nxt) {
            int nb = buf ^ 1;
            #pragma unroll
            for (int i = 0; i < QA; i++) {
                int idx = tid + i * NT;
                int r  = idx / (BK/4);
                int kq = (idx % (BK/4)) * 4;
                unsigned* p = &As[nb][r * BK1 + kq];
                p[0] = f2tf32(pa[i].x); p[1] = f2tf32(pa[i].y);
                p[2] = f2tf32(pa[i].z); p[3] = f2tf32(pa[i].w);
            }
            #pragma unroll
            for (int i = 0; i < QB; i++) {
                int idx = tid + i * NT;
                int k  = idx / (BN/4);
                int nq = (idx % (BN/4)) * 4;
                #pragma unroll
                for (int c = 0; c < 4; c++)
                    Bs[nb][(nq + c) * BK1 + k] = f2tf32(pb[i][c]);
            }
            __syncthreads();
            buf = nb;
        }
    }

    // ---- epilogue ----
    #pragma unroll
    for (int mt = 0; mt < MT; mt++) {
        int row0 = bm + warp_m * WM + mt * 16 + g;
        #pragma unroll
        for (int nt = 0; nt < NTn; nt++) {
            int col0 = bn + warp_n * WN + nt * 8 + tig * 2;
            #pragma unroll
            for (int c = 0; c < 4; c++) {
                int row = row0 + (c >= 2 ? 8 : 0);
                int col = col0 + (c & 1);
                if (col < N) {
                    float v = acc[mt][nt][c];
                    if (BIAS) v += bias[col];
                    if (GELU) v = 0.5f * v * (1.0f + erff(v * 0.70710678118654752f));
                    if (RES)  v += res[(size_t)row * N + col];
                    C[(size_t)row * N + col] = v;
                }
            }
        }
    }
}

// ---------------- causal attention (fp32, exact) ----------------
__global__ void attn_kernel(const float* __restrict__ q, const float* __restrict__ k,
                            const float* __restrict__ v, float* __restrict__ y) {
    __shared__ float sQ[HD_];
    __shared__ float sS[T_];
    __shared__ float red[128];

    int t = blockIdx.x, h = blockIdx.y, b = blockIdx.z;
    int tid = threadIdx.x;
    const size_t qoff = (size_t)(b*T_ + t) * D_ + h*HD_;

    if (tid < HD_) sQ[tid] = q[qoff + tid];
    __syncthreads();

    float lmax = -INFINITY;
    for (int j = tid; j <= t; j += 128) {
        const float* kr = k + (size_t)(b*T_ + j) * D_ + h*HD_;
        float acc = 0.0f;
        #pragma unroll
        for (int d = 0; d < HD_; d += 4) {
            float4 kv = *(const float4*)(kr + d);
            acc += sQ[d]*kv.x + sQ[d+1]*kv.y + sQ[d+2]*kv.z + sQ[d+3]*kv.w;
        }
        acc *= 0.125f;
        sS[j] = acc;
        lmax = fmaxf(lmax, acc);
    }
    red[tid] = lmax;
    __syncthreads();
    #pragma unroll
    for (int s = 64; s > 0; s >>= 1) {
        if (tid < s) red[tid] = fmaxf(red[tid], red[tid+s]);
        __syncthreads();
    }
    float mx = red[0];
    __syncthreads();

    float lsum = 0.0f;
    for (int j = tid; j <= t; j += 128) {
        float e = __expf(sS[j] - mx);
        sS[j] = e;
        lsum += e;
    }
    red[tid] = lsum;
    __syncthreads();
    #pragma unroll
    for (int s = 64; s > 0; s >>= 1) {
        if (tid < s) red[tid] += red[tid+s];
        __syncthreads();
    }
    float inv = 1.0f / red[0];
    __syncthreads();

    int d = tid & 63;
    int half = tid >> 6;
    float acc = 0.0f;
    for (int j = half; j <= t; j += 2)
        acc += sS[j] * v[(size_t)(b*T_ + j) * D_ + h*HD_ + d];
    red[tid] = acc;
    __syncthreads();
    if (tid < 64)
        y[qoff + tid] = (red[tid] + red[tid + 64]) * inv;
}

// ---------------- host orchestration ----------------
extern "C" void kernel_launch(void* const* d_in, const int* in_sizes, int n_in,
                              void* d_out, int out_size) {
    const int*   idx  = (const int*)  d_in[0];
    const float* tok  = (const float*)d_in[1];
    const float* pos  = (const float*)d_in[2];
    const float* Wq   = (const float*)d_in[3];
    const float* Wk   = (const float*)d_in[4];
    const float* Wv   = (const float*)d_in[5];
    const float* Wo   = (const float*)d_in[6];
    const float* bo   = (const float*)d_in[7];
    const float* ln1g = (const float*)d_in[8];
    const float* ln1b = (const float*)d_in[9];
    const float* Wf1  = (const float*)d_in[10];
    const float* bf1  = (const float*)d_in[11];
    const float* Wf2  = (const float*)d_in[12];
    const float* bf2  = (const float*)d_in[13];
    const float* ln2g = (const float*)d_in[14];
    const float* ln2b = (const float*)d_in[15];
    const float* lnfg = (const float*)d_in[16];
    const float* lnfb = (const float*)d_in[17];
    const float* Wlm  = (const float*)d_in[18];
    float* out = (float*)d_out;

    float *x, *h, *qb, *kb, *vb, *yb, *ffb;
    cudaGetSymbolAddress((void**)&x,   g_x);
    cudaGetSymbolAddress((void**)&h,   g_h);
    cudaGetSymbolAddress((void**)&qb,  g_q);
    cudaGetSymbolAddress((void**)&kb,  g_k);
    cudaGetSymbolAddress((void**)&vb,  g_v);
    cudaGetSymbolAddress((void**)&yb,  g_y);
    cudaGetSymbolAddress((void**)&ffb, g_ff);

    // small GEMMs (N=768): 64x64x32 tiles, 4 warps -> grid 32x12 = 384 blocks
    const dim3 gS(BT_/64, D_/64);
    // FF1 (N=3072): 128x128x16 tiles, 8 warps -> 16x24 = 384 blocks
    const dim3 gF1(BT_/128, FF_/128);
    // LM head (N=50257, odd -> scalar B path): 128x128x16 -> 16x393 blocks
    const dim3 gLM(BT_/128, (V_+127)/128);

    embed_kernel<<<(BT_*D_ + 255)/256, 256>>>(idx, tok, pos, x);

    for (int l = 0; l < L_; l++) {
        const float* wq  = Wq  + (size_t)l*D_*D_;
        const float* wk  = Wk  + (size_t)l*D_*D_;
        const float* wv  = Wv  + (size_t)l*D_*D_;
        const float* wo  = Wo  + (size_t)l*D_*D_;
        const float* wf1 = Wf1 + (size_t)l*D_*FF_;
        const float* wf2 = Wf2 + (size_t)l*FF_*D_;

        ln_kernel<<<BT_, 256>>>(x, ln1g + l*D_, ln1b + l*D_, h);
        mma_gemm<64,64,32,32,32,0,0,0><<<gS, 128>>>(h, wq, nullptr, nullptr, qb, BT_, D_, D_);
        mma_gemm<64,64,32,32,32,0,0,0><<<gS, 128>>>(h, wk, nullptr, nullptr, kb, BT_, D_, D_);
        mma_gemm<64,64,32,32,32,0,0,0><<<gS, 128>>>(h, wv, nullptr, nullptr, vb, BT_, D_, D_);
        attn_kernel<<<dim3(T_, H_, B_), 128>>>(qb, kb, vb, yb);
        mma_gemm<64,64,32,32,32,1,1,0><<<gS, 128>>>(yb, wo, bo + l*D_, x, x, BT_, D_, D_);
        ln_kernel<<<BT_, 256>>>(x, ln2g + l*D_, ln2b + l*D_, h);
        mma_gemm<128,128,16,64,32,1,0,1><<<gF1, 256>>>(h, wf1, bf1 + l*FF_, nullptr, ffb, BT_, FF_, D_);
        mma_gemm<64,64,32,32,32,1,1,0><<<gS, 128>>>(ffb, wf2, bf2 + l*D_, x, x, BT_, D_, FF_);
    }

    ln_kernel<<<BT_, 256>>>(x, lnfg, lnfb, h);
    mma_gemm<128,128,16,64,32,0,0,0><<<gLM, 256>>>(h, Wlm, nullptr, nullptr, out, BT_, V_, D_);
}

// round 13
// speedup vs baseline: 2.7542x; 1.6819x over previous
#include <cuda_runtime.h>
#include <math.h>

// GPT-2 small forward: B=2, T=1024, D=768, H=12, HD=64, L=12, V=50257
#define B_   2
#define T_   1024
#define D_   768
#define H_   12
#define HD_  64
#define L_   12
#define V_   50257
#define FF_  3072
#define BT_  (B_*T_)
#define EPS_ 1e-5f

typedef unsigned long long ull;

// ---------------- packed f32x2 helpers ----------------
__device__ __forceinline__ ull pack2(float x, float y) {
    ull r;
    asm("mov.b64 %0, {%1, %2};" : "=l"(r)
        : "r"(__float_as_uint(x)), "r"(__float_as_uint(y)));
    return r;
}
__device__ __forceinline__ ull splat2(float x) {
    ull r;
    asm("mov.b64 %0, {%1, %1};" : "=l"(r) : "r"(__float_as_uint(x)));
    return r;
}
__device__ __forceinline__ void fma2(ull& d, ull a, ull b) {
    asm("fma.rn.f32x2 %0, %1, %2, %0;" : "+l"(d) : "l"(a), "l"(b));
}
__device__ __forceinline__ void mul2(ull& d, ull a) {
    asm("mul.rn.f32x2 %0, %0, %1;" : "+l"(d) : "l"(a));
}
__device__ __forceinline__ void unpack2(ull v, float& lo, float& hi) {
    unsigned a, b;
    asm("mov.b64 {%0, %1}, %2;" : "=r"(a), "=r"(b) : "l"(v));
    lo = __uint_as_float(a); hi = __uint_as_float(b);
}

// ---------------- scratch (no cudaMalloc allowed) ----------------
__device__ float g_x  [BT_*D_];
__device__ float g_h  [BT_*D_];
__device__ float g_qkv[BT_*3*D_];
__device__ float g_y  [BT_*D_];
__device__ float g_ff [BT_*FF_];

// ---------------- tf32 helpers ----------------
__device__ __forceinline__ unsigned f2tf32(float f) {
    unsigned u;
    asm("cvt.rna.tf32.f32 %0, %1;" : "=r"(u) : "f"(f));
    return u;
}
__device__ __forceinline__ void mma_tf32(float* c, const unsigned* a, const unsigned* b) {
    asm volatile(
        "mma.sync.aligned.m16n8k8.row.col.f32.tf32.tf32.f32 "
        "{%0,%1,%2,%3}, {%4,%5,%6,%7}, {%8,%9}, {%0,%1,%2,%3};"
        : "+f"(c[0]), "+f"(c[1]), "+f"(c[2]), "+f"(c[3])
        : "r"(a[0]), "r"(a[1]), "r"(a[2]), "r"(a[3]), "r"(b[0]), "r"(b[1]));
}

// ---------------- embedding ----------------
__global__ void embed_kernel(const int* __restrict__ idx,
                             const float* __restrict__ tok,
                             const float* __restrict__ pos,
                             float* __restrict__ x) {
    int i = blockIdx.x * blockDim.x + threadIdx.x;
    if (i >= BT_*D_) return;
    int bt = i / D_, d = i - bt * D_;
    int t = bt % T_;
    x[i] = tok[(size_t)idx[bt]*D_ + d] + pos[(size_t)t*D_ + d];
}

// ---------------- layernorm ----------------
__global__ void ln_kernel(const float* __restrict__ x,
                          const float* __restrict__ g,
                          const float* __restrict__ b,
                          float* __restrict__ out) {
    __shared__ float red[256];
    int row = blockIdx.x;
    int tid = threadIdx.x;
    const float* xr = x + (size_t)row * D_;
    float v0 = xr[tid], v1 = xr[tid+256], v2 = xr[tid+512];
    red[tid] = v0 + v1 + v2;
    __syncthreads();
    #pragma unroll
    for (int s = 128; s > 0; s >>= 1) {
        if (tid < s) red[tid] += red[tid+s];
        __syncthreads();
    }
    float mean = red[0] * (1.0f / D_);
    __syncthreads();
    float d0 = v0-mean, d1 = v1-mean, d2 = v2-mean;
    red[tid] = d0*d0 + d1*d1 + d2*d2;
    __syncthreads();
    #pragma unroll
    for (int s = 128; s > 0; s >>= 1) {
        if (tid < s) red[tid] += red[tid+s];
        __syncthreads();
    }
    float rstd = rsqrtf(red[0] * (1.0f / D_) + EPS_);
    float* orow = out + (size_t)row * D_;
    orow[tid    ] = d0 * rstd * g[tid    ] + b[tid    ];
    orow[tid+256] = d1 * rstd * g[tid+256] + b[tid+256];
    orow[tid+512] = d2 * rstd * g[tid+512] + b[tid+512];
}

// ---------------- tf32 tensor-core GEMM ----------------
// C[M, ·] = A[M,K] @ Wsel[K,Nw] (+bias)(+gelu)(+residual), output stride ldc.
// Wsel chosen per column-block: sel = (blockIdx.y*BN)/Nw -> w0/w1/w2 (QKV fusion).
// For plain GEMMs pass w0==w1==w2 and ldc == Nw.
template<int BM, int BN, int BK, int WM, int WN, int BIAS, int RES, int GELU>
__global__ __launch_bounds__(32*(BM/WM)*(BN/WN))
void mma_gemm(const float* __restrict__ A,
              const float* __restrict__ w0, const float* __restrict__ w1,
              const float* __restrict__ w2,
              const float* __restrict__ bias, const float* __restrict__ res,
              float* __restrict__ C, int M, int Nw, int K, int ldc) {
    constexpr int NWM = BM / WM;
    constexpr int NWN = BN / WN;
    constexpr int NT  = 32 * NWM * NWN;
    constexpr int MT  = WM / 16;
    constexpr int NTn = WN / 8;
    constexpr int KK  = BK / 8;
    constexpr int BK1 = BK + 1;
    constexpr int QA  = BM * BK / 4 / NT;
    constexpr int QB  = BK * BN / 4 / NT;

    __shared__ unsigned As[2][BM * BK1];
    __shared__ unsigned Bs[2][BN * BK1];

    const int tid = threadIdx.x;
    const int wid = tid >> 5;
    const int lane = tid & 31;
    const int g   = lane >> 2;
    const int tig = lane & 3;
    const int warp_m = wid % NWM;
    const int warp_n = wid / NWM;
    const int bm = blockIdx.x * BM;
    const int bn_g = blockIdx.y * BN;           // global output column base
    const int sel = bn_g / Nw;
    const int bn_l = bn_g - sel * Nw;           // column base within selected W
    const float* __restrict__ W = (sel == 0) ? w0 : ((sel == 1) ? w1 : w2);
    const bool vecB = ((Nw & 3) == 0) && (bn_l + BN <= Nw);

    float acc[MT][NTn][4];
    #pragma unroll
    for (int i = 0; i < MT; i++)
        #pragma unroll
        for (int j = 0; j < NTn; j++)
            #pragma unroll
            for (int c = 0; c < 4; c++) acc[i][j][c] = 0.0f;

    // ---- prologue: stage k-tile 0 into buffer 0 ----
    #pragma unroll
    for (int i = 0; i < QA; i++) {
        int idx = tid + i * NT;
        int r  = idx / (BK/4);
        int kq = (idx % (BK/4)) * 4;
        float4 v = *(const float4*)(A + (size_t)(bm + r) * K + kq);
        unsigned* p = &As[0][r * BK1 + kq];
        p[0] = f2tf32(v.x); p[1] = f2tf32(v.y); p[2] = f2tf32(v.z); p[3] = f2tf32(v.w);
    }
    #pragma unroll
    for (int i = 0; i < QB; i++) {
        int idx = tid + i * NT;
        int k  = idx / (BN/4);
        int nq = (idx % (BN/4)) * 4;
        const float* Wr = W + (size_t)k * Nw;
        float v[4];
        if (vecB) {
            float4 t = *(const float4*)(Wr + bn_l + nq);
            v[0] = t.x; v[1] = t.y; v[2] = t.z; v[3] = t.w;
        } else {
            #pragma unroll
            for (int c = 0; c < 4; c++) {
                int col = bn_l + nq + c;
                v[c] = (col < Nw) ? Wr[col] : 0.0f;
            }
        }
        #pragma unroll
        for (int c = 0; c < 4; c++) Bs[0][(nq + c) * BK1 + k] = f2tf32(v[c]);
    }
    __syncthreads();

    int buf = 0;
    for (int k0 = 0; k0 < K; k0 += BK) {
        const bool nxt = (k0 + BK < K);
        float4 pa[QA]; float pb[QB][4];
        if (nxt) {
            #pragma unroll
            for (int i = 0; i < QA; i++) {
                int idx = tid + i * NT;
                int r  = idx / (BK/4);
                int kq = (idx % (BK/4)) * 4;
                pa[i] = *(const float4*)(A + (size_t)(bm + r) * K + k0 + BK + kq);
            }
            #pragma unroll
            for (int i = 0; i < QB; i++) {
                int idx = tid + i * NT;
                int k  = idx / (BN/4);
                int nq = (idx % (BN/4)) * 4;
                const float* Wr = W + (size_t)(k0 + BK + k) * Nw;
                if (vecB) {
                    float4 t = *(const float4*)(Wr + bn_l + nq);
                    pb[i][0] = t.x; pb[i][1] = t.y; pb[i][2] = t.z; pb[i][3] = t.w;
                } else {
                    #pragma unroll
                    for (int c = 0; c < 4; c++) {
                        int col = bn_l + nq + c;
                        pb[i][c] = (col < Nw) ? Wr[col] : 0.0f;
                    }
                }
            }
        }
        // ---- compute on current buffer ----
        #pragma unroll
        for (int kk = 0; kk < KK; kk++) {
            unsigned afr[MT][4];
            #pragma unroll
            for (int mt = 0; mt < MT; mt++) {
                int rm = warp_m * WM + mt * 16;
                const unsigned* base = &As[buf][0];
                afr[mt][0] = base[(rm + g    ) * BK1 + kk*8 + tig    ];
                afr[mt][1] = base[(rm + g + 8) * BK1 + kk*8 + tig    ];
                afr[mt][2] = base[(rm + g    ) * BK1 + kk*8 + tig + 4];
                afr[mt][3] = base[(rm + g + 8) * BK1 + kk*8 + tig + 4];
            }
            unsigned bfr[NTn][2];
            #pragma unroll
            for (int nt = 0; nt < NTn; nt++) {
                int cn = warp_n * WN + nt * 8;
                const unsigned* base = &Bs[buf][0];
                bfr[nt][0] = base[(cn + g) * BK1 + kk*8 + tig    ];
                bfr[nt][1] = base[(cn + g) * BK1 + kk*8 + tig + 4];
            }
            #pragma unroll
            for (int mt = 0; mt < MT; mt++)
                #pragma unroll
                for (int nt = 0; nt < NTn; nt++)
                    mma_tf32(acc[mt][nt], afr[mt], bfr[nt]);
        }
        // ---- store prefetched tile ----
        if (nxt) {
            int nb = buf ^ 1;
            #pragma unroll
            for (int i = 0; i < QA; i++) {
                int idx = tid + i * NT;
                int r  = idx / (BK/4);
                int kq = (idx % (BK/4)) * 4;
                unsigned* p = &As[nb][r * BK1 + kq];
                p[0] = f2tf32(pa[i].x); p[1] = f2tf32(pa[i].y);
                p[2] = f2tf32(pa[i].z); p[3] = f2tf32(pa[i].w);
            }
            #pragma unroll
            for (int i = 0; i < QB; i++) {
                int idx = tid + i * NT;
                int k  = idx / (BN/4);
                int nq = (idx % (BN/4)) * 4;
                #pragma unroll
                for (int c = 0; c < 4; c++)
                    Bs[nb][(nq + c) * BK1 + k] = f2tf32(pb[i][c]);
            }
            __syncthreads();
            buf = nb;
        }
    }

    // ---- epilogue ----
    #pragma unroll
    for (int mt = 0; mt < MT; mt++) {
        int row0 = bm + warp_m * WM + mt * 16 + g;
        #pragma unroll
        for (int nt = 0; nt < NTn; nt++) {
            int coff0 = warp_n * WN + nt * 8 + tig * 2;
            #pragma unroll
            for (int c = 0; c < 4; c++) {
                int row  = row0 + (c >= 2 ? 8 : 0);
                int coff = coff0 + (c & 1);
                if (bn_l + coff < Nw) {
                    float v = acc[mt][nt][c];
                    if (BIAS) v += bias[bn_l + coff];
                    if (GELU) v = 0.5f * v * (1.0f + erff(v * 0.70710678118654752f));
                    if (RES)  v += res[(size_t)row * ldc + bn_g + coff];
                    C[(size_t)row * ldc + bn_g + coff] = v;
                }
            }
        }
    }
}

// ---------------- tiled causal attention ----------------
// Block: 64-query tile for one (head, batch). 256 threads; thread (r,cg): row r,
// cols c = 4i+cg (i=0..15). SMEM tiles Q/K/V 64x64, stride 68 (bank-safe for the
// 4-bank-spaced quad access pattern). Online softmax, fp32 exact; AV in f32x2.
// qkv layout: [BT][3*D], q at +0, k at +D, v at +2D, head at h*64.
#define ASTR 68
#define ASMEM (3*64*ASTR*4)
__global__ __launch_bounds__(256)
void attn_kernel(const float* __restrict__ qkv, float* __restrict__ y) {
    extern __shared__ float sm[];
    float* sQ = sm;
    float* sK = sm + 64*ASTR;
    float* sV = sm + 2*64*ASTR;

    const int tid = threadIdx.x;
    const int qt = gridDim.x - 1 - blockIdx.x;   // heavy tiles first
    const int h = blockIdx.y, b = blockIdx.z;
    const int r = tid >> 2, cg = tid & 3;
    const int q0 = qt * 64;
    const int hoff = h * HD_;

    // load Q tile
    #pragma unroll
    for (int j = 0; j < 4; j++) {
        int idx = tid + j*256;
        int rr = idx >> 4, c4 = (idx & 15) * 4;
        *(float4*)&sQ[rr*ASTR + c4] =
            *(const float4*)(qkv + (size_t)(b*T_ + q0 + rr)*(3*D_) + hoff + c4);
    }

    float m = -INFINITY, l = 0.0f;
    ull o2[32];
    #pragma unroll
    for (int d = 0; d < 32; d++) o2[d] = 0ull;

    for (int kt = 0; kt <= qt; kt++) {
        __syncthreads();
        #pragma unroll
        for (int j = 0; j < 4; j++) {
            int idx = tid + j*256;
            int rr = idx >> 4, c4 = (idx & 15) * 4;
            const float* src = qkv + (size_t)(b*T_ + kt*64 + rr)*(3*D_) + hoff + c4;
            *(float4*)&sK[rr*ASTR + c4] = *(const float4*)(src + D_);
            *(float4*)&sV[rr*ASTR + c4] = *(const float4*)(src + 2*D_);
        }
        __syncthreads();

        // scores: s[i] = q[r] . k[4i+cg]
        float s[16];
        #pragma unroll
        for (int i = 0; i < 16; i++) s[i] = 0.0f;
        #pragma unroll
        for (int d4 = 0; d4 < 16; d4++) {
            float4 q4 = *(const float4*)&sQ[r*ASTR + d4*4];
            #pragma unroll
            for (int i = 0; i < 16; i++) {
                float4 k4 = *(const float4*)&sK[(4*i+cg)*ASTR + d4*4];
                s[i] += q4.x*k4.x + q4.y*k4.y + q4.z*k4.z + q4.w*k4.w;
            }
        }
        const bool diag = (kt == qt);
        float smax = -INFINITY;
        #pragma unroll
        for (int i = 0; i < 16; i++) {
            float v = s[i] * 0.125f;
            if (diag && (4*i+cg) > r) v = -INFINITY;
            s[i] = v;
            smax = fmaxf(smax, v);
        }
        smax = fmaxf(smax, __shfl_xor_sync(0xffffffffu, smax, 1));
        smax = fmaxf(smax, __shfl_xor_sync(0xffffffffu, smax, 2));
        float mnew = fmaxf(m, smax);
        float corr = __expf(m - mnew);
        float psum = 0.0f;
        #pragma unroll
        for (int i = 0; i < 16; i++) {
            s[i] = __expf(s[i] - mnew);
            psum += s[i];
        }
        psum += __shfl_xor_sync(0xffffffffu, psum, 1);
        psum += __shfl_xor_sync(0xffffffffu, psum, 2);
        l = l * corr + psum;
        m = mnew;

        ull c2 = splat2(corr);
        #pragma unroll
        for (int d = 0; d < 32; d++) mul2(o2[d], c2);
        #pragma unroll
        for (int i = 0; i < 16; i++) {
            ull p2 = splat2(s[i]);
            const float* vrow = &sV[(4*i+cg)*ASTR];
            #pragma unroll
            for (int d4 = 0; d4 < 16; d4++) {
                float4 v4 = *(const float4*)&vrow[d4*4];
                fma2(o2[2*d4  ], p2, pack2(v4.x, v4.y));
                fma2(o2[2*d4+1], p2, pack2(v4.z, v4.w));
            }
        }
    }

    // quad-reduce output, stage in sK, coalesced store
    __syncthreads();
    float inv = 1.0f / l;
    #pragma unroll
    for (int d = 0; d < 32; d++) {
        float lo, hi;
        unpack2(o2[d], lo, hi);
        lo += __shfl_xor_sync(0xffffffffu, lo, 1);
        lo += __shfl_xor_sync(0xffffffffu, lo, 2);
        hi += __shfl_xor_sync(0xffffffffu, hi, 1);
        hi += __shfl_xor_sync(0xffffffffu, hi, 2);
        if (cg == 0) {
            sK[r*ASTR + 2*d    ] = lo * inv;
            sK[r*ASTR + 2*d + 1] = hi * inv;
        }
    }
    __syncthreads();
    #pragma unroll
    for (int j = 0; j < 4; j++) {
        int idx = tid + j*256;
        int rr = idx >> 4, c4 = (idx & 15) * 4;
        *(float4*)(y + (size_t)(b*T_ + q0 + rr)*D_ + hoff + c4) =
            *(float4*)&sK[rr*ASTR + c4];
    }
}

// ---------------- host orchestration ----------------
extern "C" void kernel_launch(void* const* d_in, const int* in_sizes, int n_in,
                              void* d_out, int out_size) {
    const int*   idx  = (const int*)  d_in[0];
    const float* tok  = (const float*)d_in[1];
    const float* pos  = (const float*)d_in[2];
    const float* Wq   = (const float*)d_in[3];
    const float* Wk   = (const float*)d_in[4];
    const float* Wv   = (const float*)d_in[5];
    const float* Wo   = (const float*)d_in[6];
    const float* bo   = (const float*)d_in[7];
    const float* ln1g = (const float*)d_in[8];
    const float* ln1b = (const float*)d_in[9];
    const float* Wf1  = (const float*)d_in[10];
    const float* bf1  = (const float*)d_in[11];
    const float* Wf2  = (const float*)d_in[12];
    const float* bf2  = (const float*)d_in[13];
    const float* ln2g = (const float*)d_in[14];
    const float* ln2b = (const float*)d_in[15];
    const float* lnfg = (const float*)d_in[16];
    const float* lnfb = (const float*)d_in[17];
    const float* Wlm  = (const float*)d_in[18];
    float* out = (float*)d_out;

    float *x, *h, *qkvb, *yb, *ffb;
    cudaGetSymbolAddress((void**)&x,    g_x);
    cudaGetSymbolAddress((void**)&h,    g_h);
    cudaGetSymbolAddress((void**)&qkvb, g_qkv);
    cudaGetSymbolAddress((void**)&yb,   g_y);
    cudaGetSymbolAddress((void**)&ffb,  g_ff);

    cudaFuncSetAttribute(attn_kernel, cudaFuncAttributeMaxDynamicSharedMemorySize, ASMEM);

    const dim3 gQKV(BT_/64, 3*D_/64);      // 32 x 36 = 1152 blocks
    const dim3 gS(BT_/64, D_/64);          // 32 x 12 = 384 blocks
    const dim3 gF1(BT_/128, FF_/128);      // 16 x 24 = 384 blocks
    const dim3 gLM(BT_/128, (V_+127)/128); // 16 x 393

    embed_kernel<<<(BT_*D_ + 255)/256, 256>>>(idx, tok, pos, x);

    for (int l = 0; l < L_; l++) {
        const float* wq  = Wq  + (size_t)l*D_*D_;
        const float* wk  = Wk  + (size_t)l*D_*D_;
        const float* wv  = Wv  + (size_t)l*D_*D_;
        const float* wo  = Wo  + (size_t)l*D_*D_;
        const float* wf1 = Wf1 + (size_t)l*D_*FF_;
        const float* wf2 = Wf2 + (size_t)l*FF_*D_;

        ln_kernel<<<BT_, 256>>>(x, ln1g + l*D_, ln1b + l*D_, h);
        // fused QKV: one GEMM, output [BT, 3*D]
        mma_gemm<64,64,32,32,32,0,0,0><<<gQKV, 128>>>(h, wq, wk, wv,
            nullptr, nullptr, qkvb, BT_, D_, D_, 3*D_);
        attn_kernel<<<dim3(T_/64, H_, B_), 256, ASMEM>>>(qkvb, yb);
        mma_gemm<64,64,32,32,32,1,1,0><<<gS, 128>>>(yb, wo, wo, wo,
            bo + l*D_, x, x, BT_, D_, D_, D_);
        ln_kernel<<<BT_, 256>>>(x, ln2g + l*D_, ln2b + l*D_, h);
        mma_gemm<128,128,16,64,32,1,0,1><<<gF1, 256>>>(h, wf1, wf1, wf1,
            bf1 + l*FF_, nullptr, ffb, BT_, FF_, D_, FF_);
        mma_gemm<64,64,32,32,32,1,1,0><<<gS, 128>>>(ffb, wf2, wf2, wf2,
            bf2 + l*D_, x, x, BT_, D_, FF_, D_);
    }

    ln_kernel<<<BT_, 256>>>(x, lnfg, lnfb, h);
    mma_gemm<128,128,16,64,32,0,0,0><<<gLM, 256>>>(h, Wlm, Wlm, Wlm,
        nullptr, nullptr, out, BT_, V_, D_, V_);
}